// round 1
// baseline (speedup 1.0000x reference)
#include <cuda_runtime.h>
#include <cuda_bf16.h>

// CubePad: x [6N, C, 256, 256] -> out [6N, C, 258, 258]
// Face order per cube: 0 front, 1 right, 2 back, 3 left, 4 top, 5 down.

#define Hh 256
#define Ww 256
#define Cc 64
#define HP 258
#define WP 258
#define FACE_IN  (Hh * Ww)
#define FACE_OUT (HP * WP)

// ---------------------------------------------------------------------------
// Interior: out[nfc, h+1, w+1] = in[nfc, h, w]. One thread = 4 floats.
// Input float4 loads are 16B-aligned (row width 1024B, channel base aligned).
// Output stores are scalar (row offset +1 breaks alignment) but contiguous,
// so they coalesce into full 32B sectors anyway — DRAM-bound either way.
// ---------------------------------------------------------------------------
__global__ __launch_bounds__(256) void cubepad_interior(
    const float* __restrict__ in, float* __restrict__ out, int total_vec)
{
    int idx = blockIdx.x * blockDim.x + threadIdx.x;
    if (idx >= total_vec) return;
    int wv   = idx & 63;        // W/4 = 64 vectors per row
    int rest = idx >> 6;
    int h    = rest & 255;      // H = 256
    int nfc  = rest >> 8;

    float4 v = reinterpret_cast<const float4*>(in)[idx];
    float* o = out + (size_t)nfc * FACE_OUT + (size_t)(h + 1) * WP + (wv * 4 + 1);
    o[0] = v.x; o[1] = v.y; o[2] = v.z; o[3] = v.w;
}

// ---------------------------------------------------------------------------
// Border: per (n, f, c) fill row 0, row 257, col 0 (rows 1..256), col 257.
// 1028 elements per face-channel. Corners (p=1) are edge-replication of the
// top/down plates, i.e. clamp(col-1, 0, 255) on the plate formulas.
// ---------------------------------------------------------------------------
__global__ __launch_bounds__(256) void cubepad_border(
    const float* __restrict__ in, float* __restrict__ out, int total)
{
    int idx = blockIdx.x * blockDim.x + threadIdx.x;
    if (idx >= total) return;

    int j   = idx % 1028;
    int nfc = idx / 1028;
    int c   = nfc % Cc;
    int nf  = nfc / Cc;
    int f   = nf % 6;
    int n   = nf / 6;

    const float* base  = in + ((size_t)(n * 6) * Cc + c) * FACE_IN;
    const float* front = base + (size_t)0 * Cc * FACE_IN;
    const float* right = base + (size_t)1 * Cc * FACE_IN;
    const float* back  = base + (size_t)2 * Cc * FACE_IN;
    const float* left  = base + (size_t)3 * Cc * FACE_IN;
    const float* top   = base + (size_t)4 * Cc * FACE_IN;
    const float* down  = base + (size_t)5 * Cc * FACE_IN;

    float* o = out + (size_t)nfc * FACE_OUT;
    float val;

    if (j < 2 * WP) {
        // top row (row 0) and bottom row (row 257), 258 cols each
        bool is_top = (j < WP);
        int col = is_top ? j : (j - WP);
        int w = col - 1;
        if (w < 0) w = 0;
        if (w > Ww - 1) w = Ww - 1;

        if (is_top) {
            switch (f) {
                case 0:  val = top[(Hh - 1) * Ww + w];             break; // top last row
                case 1:  val = top[(Hh - 1 - w) * Ww + (Ww - 1)];  break; // top right col, reversed
                case 2:  val = top[0 * Ww + (Ww - 1 - w)];         break; // top first row, reversed
                case 3:  val = top[w * Ww + 0];                    break; // top left col
                case 4:  val = back[0 * Ww + (Ww - 1 - w)];        break; // back first row, reversed
                default: val = front[(Hh - 1) * Ww + w];           break; // front last row
            }
            o[0 * WP + col] = val;
        } else {
            switch (f) {
                case 0:  val = down[0 * Ww + w];                   break; // down first row
                case 1:  val = down[w * Ww + (Ww - 1)];            break; // down right col
                case 2:  val = down[(Hh - 1) * Ww + (Ww - 1 - w)]; break; // down last row, reversed
                case 3:  val = down[(Hh - 1 - w) * Ww + 0];        break; // down left col, reversed
                case 4:  val = front[0 * Ww + w];                  break; // front first row
                default: val = back[(Hh - 1) * Ww + (Ww - 1 - w)]; break; // back last row, reversed
            }
            o[(HP - 1) * WP + col] = val;
        }
    } else {
        // left col (rows 1..256) then right col (rows 1..256)
        int k = j - 2 * WP;            // 0..511
        bool is_right = (k >= Hh);
        int h = is_right ? (k - Hh) : k;

        if (!is_right) {
            switch (f) {
                case 0:  val = left[h * Ww + (Ww - 1)];             break;
                case 1:  val = front[h * Ww + (Ww - 1)];            break;
                case 2:  val = right[h * Ww + (Ww - 1)];            break;
                case 3:  val = back[h * Ww + (Ww - 1)];             break;
                case 4:  val = left[0 * Ww + h];                    break; // left first row (transposed)
                default: val = left[(Hh - 1) * Ww + (Ww - 1 - h)];  break; // left last row, reversed
            }
            o[(size_t)(h + 1) * WP + 0] = val;
        } else {
            switch (f) {
                case 0:  val = right[h * Ww + 0];                   break;
                case 1:  val = back[h * Ww + 0];                    break;
                case 2:  val = left[h * Ww + 0];                    break;
                case 3:  val = front[h * Ww + 0];                   break;
                case 4:  val = right[0 * Ww + (Ww - 1 - h)];        break; // right first row, reversed
                default: val = right[(Hh - 1) * Ww + h];            break; // right last row
            }
            o[(size_t)(h + 1) * WP + (WP - 1)] = val;
        }
    }
}

extern "C" void kernel_launch(void* const* d_in, const int* in_sizes, int n_in,
                              void* d_out, int out_size)
{
    const float* x = (const float*)d_in[0];
    float* out = (float*)d_out;

    int total_in = in_sizes[0];                 // 6N * C * H * W
    int nf = total_in / (Cc * Hh * Ww);         // 6N

    int total_vec = total_in / 4;               // interior: float4 per thread
    int blocks_i = (total_vec + 255) / 256;
    cubepad_interior<<<blocks_i, 256>>>(x, out, total_vec);

    int total_b = nf * Cc * 1028;
    int blocks_b = (total_b + 255) / 256;
    cubepad_border<<<blocks_b, 256>>>(x, out, total_b);
}

// round 2
// speedup vs baseline: 1.0279x; 1.0279x over previous
#include <cuda_runtime.h>
#include <cuda_bf16.h>

// CubePad: x [6N, C, 256, 256] -> out [6N, C, 258, 258]
// Face order per cube: 0 front, 1 right, 2 back, 3 left, 4 top, 5 down.
// Single fused kernel: first `border_blocks` CTAs do the border gather
// (latency-bound, tiny traffic), remaining CTAs stream the interior copy
// (DRAM-bound). Border work hides under interior memory stalls.

#define Hh 256
#define Ww 256
#define Cc 64
#define HP 258
#define WP 258
#define FACE_IN  (Hh * Ww)
#define FACE_OUT (HP * WP)

__device__ __forceinline__ void do_interior(
    const float* __restrict__ in, float* __restrict__ out, int idx, int total_vec)
{
    if (idx >= total_vec) return;
    int wv   = idx & 63;        // W/4 = 64 vectors per row
    int rest = idx >> 6;
    int h    = rest & 255;      // H = 256
    int nfc  = rest >> 8;

    float4 v = reinterpret_cast<const float4*>(in)[idx];
    float* o = out + (size_t)nfc * FACE_OUT + (size_t)(h + 1) * WP + (wv * 4 + 1);
    o[0] = v.x; o[1] = v.y; o[2] = v.z; o[3] = v.w;
}

__device__ __forceinline__ void do_border(
    const float* __restrict__ in, float* __restrict__ out, int idx, int total)
{
    if (idx >= total) return;

    int j   = idx % 1028;
    int nfc = idx / 1028;
    int c   = nfc % Cc;
    int nf  = nfc / Cc;
    int f   = nf % 6;
    int n   = nf / 6;

    const float* base  = in + ((size_t)(n * 6) * Cc + c) * FACE_IN;
    const float* front = base + (size_t)0 * Cc * FACE_IN;
    const float* right = base + (size_t)1 * Cc * FACE_IN;
    const float* back  = base + (size_t)2 * Cc * FACE_IN;
    const float* left  = base + (size_t)3 * Cc * FACE_IN;
    const float* top   = base + (size_t)4 * Cc * FACE_IN;
    const float* down  = base + (size_t)5 * Cc * FACE_IN;

    float* o = out + (size_t)nfc * FACE_OUT;
    float val;

    if (j < 2 * WP) {
        // top row (row 0) and bottom row (row 257), 258 cols each.
        // Corners (p=1) = edge replication of the top/down plate -> clamp.
        bool is_top = (j < WP);
        int col = is_top ? j : (j - WP);
        int w = col - 1;
        if (w < 0) w = 0;
        if (w > Ww - 1) w = Ww - 1;

        if (is_top) {
            switch (f) {
                case 0:  val = top[(Hh - 1) * Ww + w];             break;
                case 1:  val = top[(Hh - 1 - w) * Ww + (Ww - 1)];  break;
                case 2:  val = top[0 * Ww + (Ww - 1 - w)];         break;
                case 3:  val = top[w * Ww + 0];                    break;
                case 4:  val = back[0 * Ww + (Ww - 1 - w)];        break;
                default: val = front[(Hh - 1) * Ww + w];           break;
            }
            o[0 * WP + col] = val;
        } else {
            switch (f) {
                case 0:  val = down[0 * Ww + w];                   break;
                case 1:  val = down[w * Ww + (Ww - 1)];            break;
                case 2:  val = down[(Hh - 1) * Ww + (Ww - 1 - w)]; break;
                case 3:  val = down[(Hh - 1 - w) * Ww + 0];        break;
                case 4:  val = front[0 * Ww + w];                  break;
                default: val = back[(Hh - 1) * Ww + (Ww - 1 - w)]; break;
            }
            o[(HP - 1) * WP + col] = val;
        }
    } else {
        // left col then right col, rows 1..256
        int k = j - 2 * WP;            // 0..511
        bool is_right = (k >= Hh);
        int h = is_right ? (k - Hh) : k;

        if (!is_right) {
            switch (f) {
                case 0:  val = left[h * Ww + (Ww - 1)];             break;
                case 1:  val = front[h * Ww + (Ww - 1)];            break;
                case 2:  val = right[h * Ww + (Ww - 1)];            break;
                case 3:  val = back[h * Ww + (Ww - 1)];             break;
                case 4:  val = left[0 * Ww + h];                    break;
                default: val = left[(Hh - 1) * Ww + (Ww - 1 - h)];  break;
            }
            o[(size_t)(h + 1) * WP + 0] = val;
        } else {
            switch (f) {
                case 0:  val = right[h * Ww + 0];                   break;
                case 1:  val = back[h * Ww + 0];                    break;
                case 2:  val = left[h * Ww + 0];                    break;
                case 3:  val = front[h * Ww + 0];                   break;
                case 4:  val = right[0 * Ww + (Ww - 1 - h)];        break;
                default: val = right[(Hh - 1) * Ww + h];            break;
            }
            o[(size_t)(h + 1) * WP + (WP - 1)] = val;
        }
    }
}

__global__ __launch_bounds__(256) void cubepad_fused(
    const float* __restrict__ in, float* __restrict__ out,
    int border_blocks, int total_border, int total_vec)
{
    int b = blockIdx.x;
    if (b < border_blocks) {
        // border path first: latency-bound threads start early, hide under
        // the interior's DRAM-bound streaming
        int idx = b * blockDim.x + threadIdx.x;
        do_border(in, out, idx, total_border);
    } else {
        int idx = (b - border_blocks) * blockDim.x + threadIdx.x;
        do_interior(in, out, idx, total_vec);
    }
}

extern "C" void kernel_launch(void* const* d_in, const int* in_sizes, int n_in,
                              void* d_out, int out_size)
{
    const float* x = (const float*)d_in[0];
    float* out = (float*)d_out;

    int total_in = in_sizes[0];                 // 6N * C * H * W
    int nf = total_in / (Cc * Hh * Ww);         // 6N

    int total_vec = total_in / 4;               // interior float4 count
    int blocks_i  = (total_vec + 255) / 256;

    int total_b  = nf * Cc * 1028;
    int blocks_b = (total_b + 255) / 256;

    cubepad_fused<<<blocks_i + blocks_b, 256>>>(x, out, blocks_b, total_b, total_vec);
}